// round 1
// baseline (speedup 1.0000x reference)
#include <cuda_runtime.h>
#include <math.h>

#define Hh 512
#define Ww 512
#define NPIX (512*512)
#define KK 50
#define BB 16
#define SLIC_ITERS 10

// scratch (static device arrays; no dynamic allocation allowed)
__device__ double        g_accum[BB][KK][6];     // [0..2]=rgb sums, [3]=fy, [4]=fx, [5]=count
__device__ float         g_centers[BB][KK][5];
__device__ unsigned char g_labels[BB][NPIX];
__device__ double        g_colorsum[BB][3];

__device__ __forceinline__ float ratio_f() {
    // matches python: 10.0 / sqrt(262144/50) in double, used as fp32 scalar
    return (float)(10.0 / sqrt((double)NPIX / (double)KK));
}

// ---------------------------------------------------------------------------
// init: zero accumulators + grid-initialized centers (first 50 of 8x8 grid)
// ---------------------------------------------------------------------------
__global__ void init_kernel(const float* __restrict__ x) {
    int b = blockIdx.x;
    int tid = threadIdx.x;
    if (tid < KK * 6) ((double*)g_accum[b])[tid] = 0.0;
    if (b == 0 && tid >= 448 && tid < 448 + BB * 3) ((double*)g_colorsum)[tid - 448] = 0.0;
    if (tid < KK) {
        int i = tid >> 3, j = tid & 7;
        int y = 32 + 64 * i;
        int xc = 32 + 64 * j;
        const float* xb = x + (size_t)b * 3 * NPIX;
        float r  = xb[y * Ww + xc];
        float g  = xb[NPIX + y * Ww + xc];
        float bl = xb[2 * NPIX + y * Ww + xc];
        float fr = ratio_f();
        g_centers[b][tid][0] = r;
        g_centers[b][tid][1] = g;
        g_centers[b][tid][2] = bl;
        g_centers[b][tid][3] = __fmul_rn((float)y, fr);
        g_centers[b][tid][4] = __fmul_rn((float)xc, fr);
    }
}

// ---------------------------------------------------------------------------
// assign + accumulate segment sums. 1 thread = 4x4 pixel patch.
// d_j = ||c_j||^2 - 2 f.c_j   (f^2 term dropped: constant per pixel, argmin-safe)
// strict < with ascending j  ==  jnp.argmin first-index tie-break
// ---------------------------------------------------------------------------
__global__ __launch_bounds__(256) void assign_kernel(const float* __restrict__ x,
                                                     int storeLabels) {
    __shared__ float s_n0[KK], s_n1[KK], s_n2[KK], s_n3[KK], s_n4[KK], s_cc[KK];
    __shared__ double s_acc[KK * 6];

    int b   = blockIdx.y;
    int tid = threadIdx.x;

    if (tid < KK) {
        float c0 = g_centers[b][tid][0];
        float c1 = g_centers[b][tid][1];
        float c2 = g_centers[b][tid][2];
        float c3 = g_centers[b][tid][3];
        float c4 = g_centers[b][tid][4];
        s_n0[tid] = __fmul_rn(-2.0f, c0);
        s_n1[tid] = __fmul_rn(-2.0f, c1);
        s_n2[tid] = __fmul_rn(-2.0f, c2);
        s_n3[tid] = __fmul_rn(-2.0f, c3);
        s_n4[tid] = __fmul_rn(-2.0f, c4);
        float cc = __fmul_rn(c0, c0);
        cc = __fmaf_rn(c1, c1, cc);
        cc = __fmaf_rn(c2, c2, cc);
        cc = __fmaf_rn(c3, c3, cc);
        cc = __fmaf_rn(c4, c4, cc);
        s_cc[tid] = cc;
    }
    for (int i2 = tid; i2 < KK * 6; i2 += 256) s_acc[i2] = 0.0;
    __syncthreads();

    int P  = blockIdx.x * 256 + tid;     // patch id within batch, 0..16383
    int py = P >> 7;
    int px = P & 127;
    int y0 = py << 2;
    int x0 = px << 2;

    const float* xr = x + (size_t)b * 3 * NPIX;
    const float* xg = xr + NPIX;
    const float* xb = xr + 2 * NPIX;
    float fr = ratio_f();

    float fxc[4];
#pragma unroll
    for (int i = 0; i < 4; i++) fxc[i] = __fmul_rn((float)(x0 + i), fr);

    int curLab = -1;
    double a0 = 0, a1 = 0, a2 = 0, a3 = 0, a4 = 0, a5 = 0;  // cnt,r,g,b,fy,fx

#pragma unroll
    for (int half = 0; half < 2; half++) {
        int yA = y0 + half * 2;
        float4 rA = *(const float4*)(xr + yA * Ww + x0);
        float4 gA = *(const float4*)(xg + yA * Ww + x0);
        float4 bA = *(const float4*)(xb + yA * Ww + x0);
        float4 rB = *(const float4*)(xr + (yA + 1) * Ww + x0);
        float4 gB = *(const float4*)(xg + (yA + 1) * Ww + x0);
        float4 bB = *(const float4*)(xb + (yA + 1) * Ww + x0);
        float fyA = __fmul_rn((float)yA, fr);
        float fyB = __fmul_rn((float)(yA + 1), fr);

        float R[8]  = {rA.x, rA.y, rA.z, rA.w, rB.x, rB.y, rB.z, rB.w};
        float G[8]  = {gA.x, gA.y, gA.z, gA.w, gB.x, gB.y, gB.z, gB.w};
        float Bc[8] = {bA.x, bA.y, bA.z, bA.w, bB.x, bB.y, bB.z, bB.w};

        float dmin[8];
        int   lab[8];
#pragma unroll
        for (int p = 0; p < 8; p++) { dmin[p] = 3.4e38f; lab[p] = 0; }

        for (int j = 0; j < KK; j++) {
            float n0 = s_n0[j], n1 = s_n1[j], n2 = s_n2[j];
            float n3 = s_n3[j], n4 = s_n4[j], cc = s_cc[j];
            float eA = __fmaf_rn(n3, fyA, cc);
            float eB = __fmaf_rn(n3, fyB, cc);
#pragma unroll
            for (int p = 0; p < 8; p++) {
                float d = __fmaf_rn(n4, fxc[p & 3], (p < 4) ? eA : eB);
                d = __fmaf_rn(n0, R[p], d);
                d = __fmaf_rn(n1, G[p], d);
                d = __fmaf_rn(n2, Bc[p], d);
                if (d < dmin[p]) { dmin[p] = d; lab[p] = j; }
            }
        }

        // accumulate (patch is label-coherent -> few flushes)
#pragma unroll
        for (int p = 0; p < 8; p++) {
            int l = lab[p];
            if (l != curLab) {
                if (curLab >= 0) {
                    atomicAdd(&s_acc[curLab * 6 + 0], a1);
                    atomicAdd(&s_acc[curLab * 6 + 1], a2);
                    atomicAdd(&s_acc[curLab * 6 + 2], a3);
                    atomicAdd(&s_acc[curLab * 6 + 3], a4);
                    atomicAdd(&s_acc[curLab * 6 + 4], a5);
                    atomicAdd(&s_acc[curLab * 6 + 5], a0);
                }
                curLab = l;
                a0 = a1 = a2 = a3 = a4 = a5 = 0.0;
            }
            a0 += 1.0;
            a1 += (double)R[p];
            a2 += (double)G[p];
            a3 += (double)Bc[p];
            a4 += (double)((p < 4) ? fyA : fyB);
            a5 += (double)fxc[p & 3];
        }

        if (storeLabels) {
            uchar4 r0 = make_uchar4((unsigned char)lab[0], (unsigned char)lab[1],
                                    (unsigned char)lab[2], (unsigned char)lab[3]);
            uchar4 r1 = make_uchar4((unsigned char)lab[4], (unsigned char)lab[5],
                                    (unsigned char)lab[6], (unsigned char)lab[7]);
            *(uchar4*)&g_labels[b][yA * Ww + x0]       = r0;
            *(uchar4*)&g_labels[b][(yA + 1) * Ww + x0] = r1;
        }
    }
    if (curLab >= 0) {
        atomicAdd(&s_acc[curLab * 6 + 0], a1);
        atomicAdd(&s_acc[curLab * 6 + 1], a2);
        atomicAdd(&s_acc[curLab * 6 + 2], a3);
        atomicAdd(&s_acc[curLab * 6 + 3], a4);
        atomicAdd(&s_acc[curLab * 6 + 4], a5);
        atomicAdd(&s_acc[curLab * 6 + 5], a0);
    }

    __syncthreads();
    for (int i2 = tid; i2 < KK * 6; i2 += 256) {
        double v = s_acc[i2];
        if (v != 0.0) atomicAdd(&((double*)g_accum[b])[i2], v);
    }
}

// ---------------------------------------------------------------------------
// centers <- sums / max(cnt,1); zero accumulator for next pass
// ---------------------------------------------------------------------------
__global__ void update_kernel() {
    int b = blockIdx.x;
    int k = threadIdx.x;
    if (k < KK) {
        double* a = g_accum[b][k];
        double cnt = a[5];
        double dv = cnt > 1.0 ? cnt : 1.0;
#pragma unroll
        for (int c = 0; c < 5; c++) {
            g_centers[b][k][c] = (float)(a[c] / dv);
            a[c] = 0.0;
        }
        a[5] = 0.0;
    }
}

// ---------------------------------------------------------------------------
// weighted color sum: w = 1/max(cnt,1) (fp32, like JAX), acc fl(x*w) in double
// ---------------------------------------------------------------------------
__global__ __launch_bounds__(256) void weight_kernel(const float* __restrict__ x) {
    __shared__ float s_inv[KK];
    int b   = blockIdx.y;
    int tid = threadIdx.x;
    if (tid < KK) {
        float cnt = (float)g_accum[b][tid][5];
        cnt = fmaxf(cnt, 1.0f);
        s_inv[tid] = __fdiv_rn(1.0f, cnt);
    }
    __syncthreads();

    int idx = (blockIdx.x * 256 + tid) * 4;
    const float* xr = x + (size_t)b * 3 * NPIX;
    const float* xg = xr + NPIX;
    const float* xb = xr + 2 * NPIX;
    float4 R  = *(const float4*)(xr + idx);
    float4 G  = *(const float4*)(xg + idx);
    float4 Bc = *(const float4*)(xb + idx);
    uchar4 L  = *(const uchar4*)&g_labels[b][idx];

    double sr = 0, sg = 0, sb = 0;
    {
        float w = s_inv[L.x];
        sr += (double)__fmul_rn(R.x, w);  sg += (double)__fmul_rn(G.x, w);  sb += (double)__fmul_rn(Bc.x, w);
        w = s_inv[L.y];
        sr += (double)__fmul_rn(R.y, w);  sg += (double)__fmul_rn(G.y, w);  sb += (double)__fmul_rn(Bc.y, w);
        w = s_inv[L.z];
        sr += (double)__fmul_rn(R.z, w);  sg += (double)__fmul_rn(G.z, w);  sb += (double)__fmul_rn(Bc.z, w);
        w = s_inv[L.w];
        sr += (double)__fmul_rn(R.w, w);  sg += (double)__fmul_rn(G.w, w);  sb += (double)__fmul_rn(Bc.w, w);
    }
#pragma unroll
    for (int off = 16; off > 0; off >>= 1) {
        sr += __shfl_down_sync(0xffffffffu, sr, off);
        sg += __shfl_down_sync(0xffffffffu, sg, off);
        sb += __shfl_down_sync(0xffffffffu, sb, off);
    }
    if ((tid & 31) == 0) {
        atomicAdd(&g_colorsum[b][0], sr);
        atomicAdd(&g_colorsum[b][1], sg);
        atomicAdd(&g_colorsum[b][2], sb);
    }
}

// ---------------------------------------------------------------------------
// finalize: fp32 epilogue mirroring the reference formula
// ---------------------------------------------------------------------------
__global__ void finalize_kernel(float* __restrict__ out) {
    int b = threadIdx.x;
    if (b < BB) {
        float mr = (float)(g_colorsum[b][0] / (double)NPIX);
        float mg = (float)(g_colorsum[b][1] / (double)NPIX);
        float mb = (float)(g_colorsum[b][2] / (double)NPIX);
        float drg = __fadd_rn(mr, -mg);
        float drb = __fadd_rn(mr, -mb);
        float dgb = __fadd_rn(mb, -mg);
        float Drg = __fmul_rn(drg, drg);
        float Drb = __fmul_rn(drb, drb);
        float Dgb = __fmul_rn(dgb, dgb);
        float t = __fadd_rn(__fadd_rn(__fmul_rn(Drg, Drg), __fmul_rn(Drb, Drb)),
                            __fmul_rn(Dgb, Dgb));
        out[b] = __fsqrt_rn(t);
    }
}

// ---------------------------------------------------------------------------
extern "C" void kernel_launch(void* const* d_in, const int* in_sizes, int n_in,
                              void* d_out, int out_size) {
    const float* x = (const float*)d_in[0];
    float* out = (float*)d_out;

    init_kernel<<<BB, 512>>>(x);
    for (int it = 0; it < SLIC_ITERS; it++) {
        assign_kernel<<<dim3(64, BB), 256>>>(x, 0);
        update_kernel<<<BB, 64>>>();
    }
    assign_kernel<<<dim3(64, BB), 256>>>(x, 1);       // final assign, store labels + counts
    weight_kernel<<<dim3(256, BB), 256>>>(x);
    finalize_kernel<<<1, 32>>>(out);
}